// round 3
// baseline (speedup 1.0000x reference)
#include <cuda_runtime.h>

#define NT 512
#define SCALE 0.17677669529663687f

// shared memory layout (float offsets)
#define XW_OFF 0
#define XW_STR 388                     // 64 x 388
#define WB_OFF 24832                   // weight buffer: 12288 floats
#define OS_OFF 37120                   // 64 x 36 (stride 36)
#define QS_OFF 39424                   // 64 x 33
#define KS_OFF 41536                   // 64 x 33
#define VS_OFF 43648                   // 64 x 36
#define PS_OFF 45952                   // 64 x 68
#define BIAS_OFF 50304                 // 384
#define SMEM_FLOATS 50688              // 202752 bytes

__global__ void __launch_bounds__(NT, 1)
winattn_kernel(const float* __restrict__ x, const float* __restrict__ wqkv,
               const float* __restrict__ wout, const float* __restrict__ bias,
               float* __restrict__ out)
{
    extern __shared__ float sm[];
    const int tid  = threadIdx.x;
    const int lane = tid & 31;
    const int w    = tid >> 5;

    const int n  = blockIdx.x;
    const int b  = n >> 6;
    const int ih = (n >> 3) & 7;
    const int iw = n & 7;
    const long gbase = (((long)b * 64 + ih * 8) * 64 + iw * 8) * 384;

    // ---- stage x window: xw[t][d], t = r*8+c within window ----
#pragma unroll
    for (int i = 0; i < 48; i++) {
        int e = i * NT + tid;                  // 0..24575
        int t = e / 384, d = e - t * 384;
        sm[XW_OFF + t * XW_STR + d] = x[gbase + (((t >> 3) * 64) + (t & 7)) * 384 + d];
    }
    if (tid < 384) sm[BIAS_OFF + tid] = bias[tid];

    // thread mappings
    const int t0   = w * 4;                    // 4 tokens per warp (qkv + proj)
    const int c3   = lane * 3;                 // 3 qkv cols
    const int s_r  = tid >> 3;                 // scores/AV row
    const int s_c0 = (tid & 7) * 8;            // 8 score cols
    const int a_d0 = (tid & 7) * 4;            // 4 AV dims
    const int pc0  = lane * 12;                // 12 proj cols

    float oacc[4][12];
#pragma unroll
    for (int i = 0; i < 4; i++)
#pragma unroll
        for (int j = 0; j < 12; j++) oacc[i][j] = 0.f;

    for (int h = 0; h < 12; h++) {
        // ================= QKV GEMM: C[64][96] =================
        float acc[4][3];
#pragma unroll
        for (int i = 0; i < 4; i++) { acc[i][0] = acc[i][1] = acc[i][2] = 0.f; }

        for (int kc = 0; kc < 6; kc++) {
            __syncthreads();                   // protect WB from previous phase readers
#pragma unroll
            for (int i = 0; i < 12; i++) {
                int e = i * NT + tid;          // 0..6143
                int k = e / 96, c = e - k * 96;
                int gc = (c >> 5) * 384 + h * 32 + (c & 31);
                sm[WB_OFF + e] = wqkv[(kc * 64 + k) * 1152 + gc];
            }
            __syncthreads();
            const float* xwp = &sm[XW_OFF + t0 * XW_STR + kc * 64];
            const float* wsp = &sm[WB_OFF + c3];
#pragma unroll 8
            for (int k = 0; k < 64; k++) {
                float b0 = wsp[k * 96 + 0];
                float b1 = wsp[k * 96 + 1];
                float b2 = wsp[k * 96 + 2];
#pragma unroll
                for (int i = 0; i < 4; i++) {
                    float a = xwp[i * XW_STR + k];
                    acc[i][0] = fmaf(a, b0, acc[i][0]);
                    acc[i][1] = fmaf(a, b1, acc[i][1]);
                    acc[i][2] = fmaf(a, b2, acc[i][2]);
                }
            }
        }
        __syncthreads();
        // scatter C to q (scaled), k, v
#pragma unroll
        for (int i = 0; i < 4; i++) {
            int t = t0 + i;
#pragma unroll
            for (int j = 0; j < 3; j++) {
                int c = c3 + j;
                float v = acc[i][j];
                if (c < 32)      sm[QS_OFF + t * 33 + c]      = v * SCALE;
                else if (c < 64) sm[KS_OFF + t * 33 + c - 32] = v;
                else             sm[VS_OFF + t * 36 + c - 64] = v;
            }
        }
        __syncthreads();

        // ================= scores + softmax (registers) =================
        float sc[8];
#pragma unroll
        for (int j = 0; j < 8; j++) sc[j] = 0.f;
        const float* qp = &sm[QS_OFF + s_r * 33];
        const float* kp = &sm[KS_OFF + s_c0 * 33];
#pragma unroll 4
        for (int d = 0; d < 32; d++) {
            float qv = qp[d];
#pragma unroll
            for (int j = 0; j < 8; j++)
                sc[j] = fmaf(qv, kp[j * 33 + d], sc[j]);
        }
        float m = sc[0];
#pragma unroll
        for (int j = 1; j < 8; j++) m = fmaxf(m, sc[j]);
#pragma unroll
        for (int msk = 1; msk < 8; msk <<= 1)
            m = fmaxf(m, __shfl_xor_sync(0xffffffffu, m, msk));
        float ssum = 0.f;
#pragma unroll
        for (int j = 0; j < 8; j++) { sc[j] = __expf(sc[j] - m); ssum += sc[j]; }
#pragma unroll
        for (int msk = 1; msk < 8; msk <<= 1)
            ssum += __shfl_xor_sync(0xffffffffu, ssum, msk);
        float inv = 1.f / ssum;
#pragma unroll
        for (int j = 0; j < 8; j++)
            sm[PS_OFF + s_r * 68 + s_c0 + j] = sc[j] * inv;
        __syncthreads();

        // ================= AV: o[64][32] =================
        float av0 = 0.f, av1 = 0.f, av2 = 0.f, av3 = 0.f;
        const float* pp = &sm[PS_OFF + s_r * 68];
#pragma unroll 8
        for (int j = 0; j < 64; j++) {
            float p = pp[j];
            float4 v4 = *(const float4*)&sm[VS_OFF + j * 36 + a_d0];
            av0 = fmaf(p, v4.x, av0);
            av1 = fmaf(p, v4.y, av1);
            av2 = fmaf(p, v4.z, av2);
            av3 = fmaf(p, v4.w, av3);
        }
        {
            float4 o4 = make_float4(av0, av1, av2, av3);
            *(float4*)&sm[OS_OFF + s_r * 36 + a_d0] = o4;
        }
        __syncthreads();

        // ================= incremental out-projection =================
        // load wout rows h*32..h*32+31 (all 384 cols) into WB
#pragma unroll
        for (int i = 0; i < 24; i++) {
            int e = i * NT + tid;              // 0..12287
            int r = e / 384, c = e - r * 384;
            sm[WB_OFF + e] = wout[(h * 32 + r) * 384 + c];
        }
        __syncthreads();
        const float* osp = &sm[OS_OFF + t0 * 36];
        const float* wpp = &sm[WB_OFF + pc0];
#pragma unroll 4
        for (int dd = 0; dd < 32; dd++) {
            float4 w0 = *(const float4*)&wpp[dd * 384 + 0];
            float4 w1 = *(const float4*)&wpp[dd * 384 + 4];
            float4 w2 = *(const float4*)&wpp[dd * 384 + 8];
#pragma unroll
            for (int i = 0; i < 4; i++) {
                float a = osp[i * 36 + dd];
                oacc[i][0]  = fmaf(a, w0.x, oacc[i][0]);
                oacc[i][1]  = fmaf(a, w0.y, oacc[i][1]);
                oacc[i][2]  = fmaf(a, w0.z, oacc[i][2]);
                oacc[i][3]  = fmaf(a, w0.w, oacc[i][3]);
                oacc[i][4]  = fmaf(a, w1.x, oacc[i][4]);
                oacc[i][5]  = fmaf(a, w1.y, oacc[i][5]);
                oacc[i][6]  = fmaf(a, w1.z, oacc[i][6]);
                oacc[i][7]  = fmaf(a, w1.w, oacc[i][7]);
                oacc[i][8]  = fmaf(a, w2.x, oacc[i][8]);
                oacc[i][9]  = fmaf(a, w2.y, oacc[i][9]);
                oacc[i][10] = fmaf(a, w2.z, oacc[i][10]);
                oacc[i][11] = fmaf(a, w2.w, oacc[i][11]);
            }
        }
        // WB/OS rewritten only after syncs at the top of next head's phases
    }

    // ================= bias + coalesced store =================
    float4 b0 = *(const float4*)&sm[BIAS_OFF + pc0 + 0];
    float4 b1 = *(const float4*)&sm[BIAS_OFF + pc0 + 4];
    float4 b2 = *(const float4*)&sm[BIAS_OFF + pc0 + 8];
#pragma unroll
    for (int i = 0; i < 4; i++) {
        int t = t0 + i;
        long go = gbase + (((t >> 3) * 64) + (t & 7)) * 384 + pc0;
        float4 o0 = make_float4(oacc[i][0] + b0.x, oacc[i][1] + b0.y,
                                oacc[i][2] + b0.z, oacc[i][3] + b0.w);
        float4 o1 = make_float4(oacc[i][4] + b1.x, oacc[i][5] + b1.y,
                                oacc[i][6] + b1.z, oacc[i][7] + b1.w);
        float4 o2 = make_float4(oacc[i][8] + b2.x, oacc[i][9] + b2.y,
                                oacc[i][10] + b2.z, oacc[i][11] + b2.w);
        *(float4*)&out[go + 0] = o0;
        *(float4*)&out[go + 4] = o1;
        *(float4*)&out[go + 8] = o2;
    }
}

extern "C" void kernel_launch(void* const* d_in, const int* in_sizes, int n_in,
                              void* d_out, int out_size)
{
    const float* x    = (const float*)d_in[0];
    const float* wqkv = (const float*)d_in[1];
    const float* wout = (const float*)d_in[2];
    const float* bout = (const float*)d_in[3];
    float* out = (float*)d_out;

    static bool attr_set = false;
    if (!attr_set) {
        cudaFuncSetAttribute(winattn_kernel,
                             cudaFuncAttributeMaxDynamicSharedMemorySize,
                             SMEM_FLOATS * sizeof(float));
        attr_set = true;
    }
    winattn_kernel<<<2048, NT, SMEM_FLOATS * sizeof(float)>>>(x, wqkv, wout, bout, out);
}